// round 15
// baseline (speedup 1.0000x reference)
#include <cuda_runtime.h>
#include <cuda_bf16.h>
#include <math.h>

// Problem constants
#define NN 8192
#define CH 32
#define NP (NN / 16)    // packed u32 words per adj row
#define KSP 16          // j-splits for gcn
#define JR (NN / KSP)   // 512 j per split
#define CHUNK 128
#define NCHUNK (JR / CHUNK)                 // 4
#define SBUF (3 * 128 * 40)                 // bf16 elems per buffer
#define GCN_SMEM (2 * SBUF * 2)             // bytes, double-buffered (61440)

// ---------------- device scratch (no allocation allowed) ----------------
__device__ __align__(256) unsigned g_A[(long)NN * NP];          // 2-bit packed adj (16 MB)
__device__ __align__(256) __nv_bfloat16 g_H[3L * NN * CH];      // H bf16 [plane][j][c]
__device__ float g_P[(long)KSP * NN * CH];                      // k-split fp32 partials (16 MB)
__device__ float g_pool[256 * CH];                              // per-block pooling partials

// ---------------------------------------------------------------------------
// prep: FUSED repack + hgen(layer 0), partitioned by blockIdx.x. (R14-verified)
// ---------------------------------------------------------------------------
__global__ __launch_bounds__(256) void prep_kernel(const int* __restrict__ adj,
                                                   const float* __restrict__ V,
                                                   const float* __restrict__ w1,
                                                   const float* __restrict__ w2,
                                                   const float* __restrict__ w3) {
    __shared__ float sw[3][32][32];
    __shared__ float sZ[32][33];
    const int tid = threadIdx.x;

    if (blockIdx.x >= 256) {
        const long idx = (long)(blockIdx.x - 256) * 256 + tid;  // 0 .. 4M-1
        const int4* src = (const int4*)(adj + idx * 16);
        unsigned w = 0;
#pragma unroll
        for (int q = 0; q < 4; q++) {
            int4 a = src[q];
            unsigned b = (unsigned)(a.x & 3) | ((unsigned)(a.y & 3) << 2) |
                         ((unsigned)(a.z & 3) << 4) | ((unsigned)(a.w & 3) << 6);
            w |= b << (q * 8);
        }
        g_A[idx] = w;
        return;
    }

#pragma unroll
    for (int q = 0; q < 4; q++) {
        int id = tid + q * 256;
        sw[0][id >> 5][id & 31] = w1[id];
        sw[1][id >> 5][id & 31] = w2[id];
        sw[2][id >> 5][id & 31] = w3[id];
    }
    const int c = tid & 31, w = tid >> 5;
    const int j0 = blockIdx.x * 32;
#pragma unroll
    for (int rr = 0; rr < 4; rr++) {
        const int lr = w * 4 + rr;
        sZ[lr][c] = V[(long)(j0 + lr) * CH + c];
    }
    __syncthreads();
#pragma unroll
    for (int rr = 0; rr < 4; rr++) {
        const int lr = w * 4 + rr;
        const long row = j0 + lr;
        float a0 = 0.f, a1 = 0.f, a2 = 0.f;
#pragma unroll
        for (int d = 0; d < 32; d++) {
            float zd = sZ[lr][d];
            a0 += zd * sw[0][d][c];
            a1 += zd * sw[1][d][c];
            a2 += zd * sw[2][d][c];
        }
        g_H[(0L * NN + row) * CH + c] = __float2bfloat16(a0);
        g_H[(1L * NN + row) * CH + c] = __float2bfloat16(a1);
        g_H[(2L * NN + row) * CH + c] = __float2bfloat16(a2);
    }
}

// ---------------------------------------------------------------------------
// hgen (layer 1): Z = relu(gb0 + sum_s P[s]); H_k = Z @ w_k. (R14-verified)
// ---------------------------------------------------------------------------
__global__ __launch_bounds__(256, 2) void hgen_kernel(const float* __restrict__ bias,
                                                      const float* __restrict__ w1,
                                                      const float* __restrict__ w2,
                                                      const float* __restrict__ w3) {
    __shared__ float sw[3][32][32];
    __shared__ float sZ[32][33];
    const int tid = threadIdx.x;
#pragma unroll
    for (int q = 0; q < 4; q++) {
        int id = tid + q * 256;
        sw[0][id >> 5][id & 31] = w1[id];
        sw[1][id >> 5][id & 31] = w2[id];
        sw[2][id >> 5][id & 31] = w3[id];
    }
    const int c = tid & 31, w = tid >> 5;
    const int j0 = blockIdx.x * 32;
#pragma unroll
    for (int rr = 0; rr < 4; rr++) {
        const int lr = w * 4 + rr, row = j0 + lr;
        float s = 0.f;
#pragma unroll
        for (int p = 0; p < KSP; p++) s += g_P[((long)p * NN + row) * CH + c];
        sZ[lr][c] = fmaxf(bias[c] + s, 0.f);
    }
    __syncthreads();
#pragma unroll
    for (int rr = 0; rr < 4; rr++) {
        const int lr = w * 4 + rr;
        const long row = j0 + lr;
        float a0 = 0.f, a1 = 0.f, a2 = 0.f;
#pragma unroll
        for (int d = 0; d < 32; d++) {
            float zd = sZ[lr][d];
            a0 += zd * sw[0][d][c];
            a1 += zd * sw[1][d][c];
            a2 += zd * sw[2][d][c];
        }
        g_H[(0L * NN + row) * CH + c] = __float2bfloat16(a0);
        g_H[(1L * NN + row) * CH + c] = __float2bfloat16(a1);
        g_H[(2L * NN + row) * CH + c] = __float2bfloat16(a2);
    }
}

// ---------------------------------------------------------------------------
// gcn: masked matmul. grid (32 m-tiles x 256 rows, KSP), 256 threads.
// Warp owns 32 m-rows (two 16-row groups): each ldmatrix B fragment feeds
// TWO A-groups -> LDSM traffic halved. cp.async double-buffered H staging.
// ---------------------------------------------------------------------------
__device__ __forceinline__ void mma_bf16(float* c, const unsigned* a,
                                         unsigned b0, unsigned b1) {
    asm volatile(
        "mma.sync.aligned.m16n8k16.row.col.f32.bf16.bf16.f32 "
        "{%0,%1,%2,%3},{%4,%5,%6,%7},{%8,%9},{%0,%1,%2,%3};"
        : "+f"(c[0]), "+f"(c[1]), "+f"(c[2]), "+f"(c[3])
        : "r"(a[0]), "r"(a[1]), "r"(a[2]), "r"(a[3]), "r"(b0), "r"(b1));
}

__device__ __forceinline__ void ldmx4t(unsigned& d0, unsigned& d1,
                                       unsigned& d2, unsigned& d3, unsigned addr) {
    asm volatile(
        "ldmatrix.sync.aligned.m8n8.x4.trans.shared.b16 {%0,%1,%2,%3}, [%4];"
        : "=r"(d0), "=r"(d1), "=r"(d2), "=r"(d3)
        : "r"(addr));
}

__device__ __forceinline__ void cpa16(unsigned dst, const void* src) {
    asm volatile("cp.async.cg.shared.global [%0], [%1], 16;" :: "r"(dst), "l"(src));
}

__global__ __launch_bounds__(256, 2) void gcn_kernel() {
    extern __shared__ __align__(16) __nv_bfloat16 s_H[];   // 2 x 3 x 128 x 40

    const int tid = threadIdx.x;
    const int warp = tid >> 5, lane = tid & 31;
    const int g = lane >> 2, t = lane & 3;
    const int i0 = blockIdx.x * 256;
    const int ksp = blockIdx.y;
    const long jbase = (long)ksp * JR;

    float acc[32];
#pragma unroll
    for (int x = 0; x < 32; x++) acc[x] = 0.f;

    const unsigned sH_base = (unsigned)__cvta_generic_to_shared(s_H);
    const unsigned lm_row = lane & 15;
    const unsigned lm_col = (lane >> 4) * 8;
    const int r0 = i0 + warp * 32 + g;
    const unsigned* ap = g_A + (long)r0 * NP + (jbase >> 4);   // row g (group0)

    // stage chunk 0 into buf 0
#pragma unroll
    for (int q = 0; q < 6; q++) {
        int id = tid + q * 256;
        int plane = id >> 9, rem = id & 511;
        int row = rem >> 2, c4 = rem & 3;
        cpa16(sH_base + (unsigned)(((plane * 128 + row) * 40 + c4 * 8) * 2),
              g_H + ((long)plane * NN + jbase + row) * CH + c4 * 8);
    }
    asm volatile("cp.async.commit_group;" ::: "memory");

    for (int it = 0; it < NCHUNK; it++) {
        const int buf = it & 1;
        __syncthreads();                       // prev compute done (protects buf^1)
        if (it + 1 < NCHUNK) {
            const long jb = jbase + (long)(it + 1) * CHUNK;
            const unsigned boff = (unsigned)((buf ^ 1) * SBUF * 2);
#pragma unroll
            for (int q = 0; q < 6; q++) {
                int id = tid + q * 256;
                int plane = id >> 9, rem = id & 511;
                int row = rem >> 2, c4 = rem & 3;
                cpa16(sH_base + boff + (unsigned)(((plane * 128 + row) * 40 + c4 * 8) * 2),
                      g_H + ((long)plane * NN + jb + row) * CH + c4 * 8);
            }
            asm volatile("cp.async.commit_group;" ::: "memory");
            asm volatile("cp.async.wait_group 1;" ::: "memory");
        } else {
            asm volatile("cp.async.wait_group 0;" ::: "memory");
        }
        __syncthreads();                       // staged data visible to all warps

        const unsigned sbuf = sH_base + (unsigned)(buf * SBUF * 2);
        const int jsb = it * CHUNK;
#pragma unroll
        for (int jo = 0; jo < CHUNK; jo += 32) {
            const int jc = jsb + jo;
            const uint2 wA = *(const uint2*)(ap + (jc >> 4));              // row g
            const uint2 wB = *(const uint2*)(ap + 8L * NP + (jc >> 4));    // row g+8
            const uint2 wC = *(const uint2*)(ap + 16L * NP + (jc >> 4));   // row g+16
            const uint2 wD = *(const uint2*)(ap + 24L * NP + (jc >> 4));   // row g+24
#pragma unroll
            for (int ks = 0; ks < 2; ks++) {
                const unsigned pA = ks ? wA.y : wA.x;
                const unsigned pB = ks ? wB.y : wB.x;
                const unsigned pC = ks ? wC.y : wC.x;
                const unsigned pD = ks ? wD.y : wD.x;
                unsigned e0 = (pA >> (4 * t)) & 0xFu;
                unsigned e1 = (pB >> (4 * t)) & 0xFu;
                unsigned e2 = (pA >> (16 + 4 * t)) & 0xFu;
                unsigned e3 = (pB >> (16 + 4 * t)) & 0xFu;
                unsigned e4 = (pC >> (4 * t)) & 0xFu;
                unsigned e5 = (pD >> (4 * t)) & 0xFu;
                unsigned e6 = (pC >> (16 + 4 * t)) & 0xFu;
                unsigned e7 = (pD >> (16 + 4 * t)) & 0xFu;

                unsigned A1[8], A2[8], A3[8];
#define MK(E, i)                                                              \
                {                                                             \
                    unsigned sel = ((E) & 3u) * 0x11u + ((E) >> 2) * 0x1100u + 0x4040u; \
                    A1[i] = __byte_perm(0x00008000u, 0x00003F00u, sel);       \
                    A2[i] = __byte_perm(0x00800000u, 0x003F0000u, sel);       \
                    A3[i] = __byte_perm(0x80000000u, 0x3F000000u, sel);       \
                }
                MK(e0, 0) MK(e1, 1) MK(e2, 2) MK(e3, 3)
                MK(e4, 4) MK(e5, 5) MK(e6, 6) MK(e7, 7)
#undef MK

#pragma unroll
                for (int m = 0; m < 3; m++) {
                    const unsigned* Am = (m == 0) ? A1 : ((m == 1) ? A2 : A3);
                    unsigned base = sbuf +
                        (((unsigned)(m * 128 + jo) + ks * 16 + lm_row) * 40 + lm_col) * 2;
                    unsigned b0, b1, b2, b3;
                    ldmx4t(b0, b1, b2, b3, base);          // n 0..15 (both groups)
                    mma_bf16(acc + 0,  Am,     b0, b1);
                    mma_bf16(acc + 4,  Am,     b2, b3);
                    mma_bf16(acc + 16, Am + 4, b0, b1);
                    mma_bf16(acc + 20, Am + 4, b2, b3);
                    ldmx4t(b0, b1, b2, b3, base + 32);     // n 16..31
                    mma_bf16(acc + 8,  Am,     b0, b1);
                    mma_bf16(acc + 12, Am,     b2, b3);
                    mma_bf16(acc + 24, Am + 4, b0, b1);
                    mma_bf16(acc + 28, Am + 4, b2, b3);
                }
            }
        }
    }

    // fp32 partials (deterministic; reduced downstream)
    float* P = g_P + ((long)ksp * NN + i0 + warp * 32) * CH;
#pragma unroll
    for (int nt = 0; nt < 4; nt++) {
        int c = nt * 8 + 2 * t;
        *(float2*)(P + (g)      * CH + c) = make_float2(acc[nt * 4 + 0],      acc[nt * 4 + 1]);
        *(float2*)(P + (g + 8)  * CH + c) = make_float2(acc[nt * 4 + 2],      acc[nt * 4 + 3]);
        *(float2*)(P + (g + 16) * CH + c) = make_float2(acc[16 + nt * 4 + 0], acc[16 + nt * 4 + 1]);
        *(float2*)(P + (g + 24) * CH + c) = make_float2(acc[16 + nt * 4 + 2], acc[16 + nt * 4 + 3]);
    }
}

// ---------------------------------------------------------------------------
// finish2: pooled sums of relu(gb1 + sum_s P[s]). grid 256 x 256.
// ---------------------------------------------------------------------------
__global__ __launch_bounds__(256, 2) void finish2_kernel(const float* __restrict__ bias) {
    __shared__ float sred[8][32];
    const int c = threadIdx.x & 31, w = threadIdx.x >> 5;
    const int j0 = blockIdx.x * 32;
    const float b = bias[c];
    float local = 0.f;
#pragma unroll
    for (int rr = 0; rr < 4; rr++) {
        const int row = j0 + w * 4 + rr;
        float s = 0.f;
#pragma unroll
        for (int p = 0; p < KSP; p++) s += g_P[((long)p * NN + row) * CH + c];
        local += fmaxf(b + s, 0.f);
    }
    sred[w][c] = local;
    __syncthreads();
    if (w == 0) {
        float tt = sred[0][c];
#pragma unroll
        for (int q = 1; q < 8; q++) tt += sred[q][c];
        g_pool[blockIdx.x * 32 + c] = tt;
    }
}

// ---------------------------------------------------------------------------
// final: pool -> fc0(relu) -> fc1 -> sigmoid. 1 block, 256 threads.
// ---------------------------------------------------------------------------
__global__ void final_kernel(const float* __restrict__ fcW0, const float* __restrict__ fcb0,
                             const float* __restrict__ fcW1, const float* __restrict__ fcb1,
                             float* __restrict__ out) {
    __shared__ float sred[8][32];
    __shared__ float pool[32];
    const int c = threadIdx.x & 31, w = threadIdx.x >> 5;
    float s = 0.f;
    for (int i = 0; i < 32; i++) s += g_pool[(w * 32 + i) * 32 + c];
    sred[w][c] = s;
    __syncthreads();
    if (w == 0) {
        float p = sred[0][c];
#pragma unroll
        for (int q = 1; q < 8; q++) p += sred[q][c];
        pool[c] = p;
        __syncwarp();
        float o = fcb0[c];
#pragma unroll
        for (int d = 0; d < 32; d++) o += pool[d] * fcW0[c * 32 + d];
        o = fmaxf(o, 0.f);
        float v = o * fcW1[c];
#pragma unroll
        for (int off = 16; off; off >>= 1) v += __shfl_xor_sync(0xffffffffu, v, off);
        if (c == 0) out[0] = 1.f / (1.f + expf(-(v + fcb1[0])));
    }
}

// ---------------------------------------------------------------------------
extern "C" void kernel_launch(void* const* d_in, const int* in_sizes, int n_in,
                              void* d_out, int out_size) {
    (void)in_sizes; (void)n_in; (void)out_size;
    const float* V    = (const float*)d_in[0];
    const int*   adj  = (const int*)d_in[1];
    const float* w1_0 = (const float*)d_in[2];
    const float* w2_0 = (const float*)d_in[3];
    const float* w3_0 = (const float*)d_in[4];
    const float* gb_0 = (const float*)d_in[5];
    const float* w1_1 = (const float*)d_in[6];
    const float* w2_1 = (const float*)d_in[7];
    const float* w3_1 = (const float*)d_in[8];
    const float* gb_1 = (const float*)d_in[9];
    const float* fcW0 = (const float*)d_in[10];
    const float* fcb0 = (const float*)d_in[11];
    const float* fcW1 = (const float*)d_in[12];
    const float* fcb1 = (const float*)d_in[13];

    static bool attr_set = false;
    if (!attr_set) {
        cudaFuncSetAttribute(gcn_kernel, cudaFuncAttributeMaxDynamicSharedMemorySize,
                             GCN_SMEM);
        attr_set = true;
    }

    dim3 gG(32, KSP);

    prep_kernel<<<256 + NN * NP / 256, 256>>>(adj, V, w1_0, w2_0, w3_0);  // repack + H(L1)
    gcn_kernel<<<gG, 256, GCN_SMEM>>>();                       // layer-1 masked matmul
    hgen_kernel<<<256, 256>>>(gb_0, w1_1, w2_1, w3_1);         // Z=relu(..), H planes (L2)
    gcn_kernel<<<gG, 256, GCN_SMEM>>>();                       // layer-2 masked matmul
    finish2_kernel<<<256, 256>>>(gb_1);                        // relu+bias+pool partials
    final_kernel<<<1, 256>>>(fcW0, fcb0, fcW1, fcb1, (float*)d_out);
}

// round 16
// speedup vs baseline: 1.4099x; 1.4099x over previous
#include <cuda_runtime.h>
#include <cuda_bf16.h>
#include <math.h>

// Problem constants
#define NN 8192
#define CH 32
#define NP (NN / 16)    // packed u32 words per adj row
#define KSP 16          // j-splits for gcn
#define JR (NN / KSP)   // 512 j per split

// ---------------- device scratch (no allocation allowed) ----------------
__device__ __align__(256) unsigned g_A[(long)NN * NP];          // 2-bit packed adj (16 MB)
__device__ __align__(256) __nv_bfloat16 g_H[3L * NN * CH];      // H bf16 [plane][j][c]
__device__ float g_P[(long)KSP * NN * CH];                      // k-split fp32 partials (16 MB)
__device__ float g_pool[256 * CH];                              // per-block pooling partials

// ---------------------------------------------------------------------------
// prep: FUSED repack + hgen(layer 0), partitioned by blockIdx.x. (R14-verified)
// ---------------------------------------------------------------------------
__global__ __launch_bounds__(256) void prep_kernel(const int* __restrict__ adj,
                                                   const float* __restrict__ V,
                                                   const float* __restrict__ w1,
                                                   const float* __restrict__ w2,
                                                   const float* __restrict__ w3) {
    __shared__ float sw[3][32][32];
    __shared__ float sZ[32][33];
    const int tid = threadIdx.x;

    if (blockIdx.x >= 256) {
        const long idx = (long)(blockIdx.x - 256) * 256 + tid;  // 0 .. 4M-1
        const int4* src = (const int4*)(adj + idx * 16);
        unsigned w = 0;
#pragma unroll
        for (int q = 0; q < 4; q++) {
            int4 a = src[q];
            unsigned b = (unsigned)(a.x & 3) | ((unsigned)(a.y & 3) << 2) |
                         ((unsigned)(a.z & 3) << 4) | ((unsigned)(a.w & 3) << 6);
            w |= b << (q * 8);
        }
        g_A[idx] = w;
        return;
    }

#pragma unroll
    for (int q = 0; q < 4; q++) {
        int id = tid + q * 256;
        sw[0][id >> 5][id & 31] = w1[id];
        sw[1][id >> 5][id & 31] = w2[id];
        sw[2][id >> 5][id & 31] = w3[id];
    }
    const int c = tid & 31, w = tid >> 5;
    const int j0 = blockIdx.x * 32;
#pragma unroll
    for (int rr = 0; rr < 4; rr++) {
        const int lr = w * 4 + rr;
        sZ[lr][c] = V[(long)(j0 + lr) * CH + c];
    }
    __syncthreads();
#pragma unroll
    for (int rr = 0; rr < 4; rr++) {
        const int lr = w * 4 + rr;
        const long row = j0 + lr;
        float a0 = 0.f, a1 = 0.f, a2 = 0.f;
#pragma unroll
        for (int d = 0; d < 32; d++) {
            float zd = sZ[lr][d];
            a0 += zd * sw[0][d][c];
            a1 += zd * sw[1][d][c];
            a2 += zd * sw[2][d][c];
        }
        g_H[(0L * NN + row) * CH + c] = __float2bfloat16(a0);
        g_H[(1L * NN + row) * CH + c] = __float2bfloat16(a1);
        g_H[(2L * NN + row) * CH + c] = __float2bfloat16(a2);
    }
}

// ---------------------------------------------------------------------------
// hgen (layer 1): Z = relu(gb0 + sum_s P[s]); H_k = Z @ w_k. (R14-verified)
// ---------------------------------------------------------------------------
__global__ __launch_bounds__(256, 2) void hgen_kernel(const float* __restrict__ bias,
                                                      const float* __restrict__ w1,
                                                      const float* __restrict__ w2,
                                                      const float* __restrict__ w3) {
    __shared__ float sw[3][32][32];
    __shared__ float sZ[32][33];
    const int tid = threadIdx.x;
#pragma unroll
    for (int q = 0; q < 4; q++) {
        int id = tid + q * 256;
        sw[0][id >> 5][id & 31] = w1[id];
        sw[1][id >> 5][id & 31] = w2[id];
        sw[2][id >> 5][id & 31] = w3[id];
    }
    const int c = tid & 31, w = tid >> 5;
    const int j0 = blockIdx.x * 32;
#pragma unroll
    for (int rr = 0; rr < 4; rr++) {
        const int lr = w * 4 + rr, row = j0 + lr;
        float s = 0.f;
#pragma unroll
        for (int p = 0; p < KSP; p++) s += g_P[((long)p * NN + row) * CH + c];
        sZ[lr][c] = fmaxf(bias[c] + s, 0.f);
    }
    __syncthreads();
#pragma unroll
    for (int rr = 0; rr < 4; rr++) {
        const int lr = w * 4 + rr;
        const long row = j0 + lr;
        float a0 = 0.f, a1 = 0.f, a2 = 0.f;
#pragma unroll
        for (int d = 0; d < 32; d++) {
            float zd = sZ[lr][d];
            a0 += zd * sw[0][d][c];
            a1 += zd * sw[1][d][c];
            a2 += zd * sw[2][d][c];
        }
        g_H[(0L * NN + row) * CH + c] = __float2bfloat16(a0);
        g_H[(1L * NN + row) * CH + c] = __float2bfloat16(a1);
        g_H[(2L * NN + row) * CH + c] = __float2bfloat16(a2);
    }
}

// ---------------------------------------------------------------------------
// gcn: masked matmul from packed adj + bf16 H. grid (64 m-tiles, KSP), 256 thr.
// R9/R12-verified mainloop (64 regs), 4 CTAs/SM for latency hiding.
// ---------------------------------------------------------------------------
__device__ __forceinline__ void mma_bf16(float* c, const unsigned* a,
                                         unsigned b0, unsigned b1) {
    asm volatile(
        "mma.sync.aligned.m16n8k16.row.col.f32.bf16.bf16.f32 "
        "{%0,%1,%2,%3},{%4,%5,%6,%7},{%8,%9},{%0,%1,%2,%3};"
        : "+f"(c[0]), "+f"(c[1]), "+f"(c[2]), "+f"(c[3])
        : "r"(a[0]), "r"(a[1]), "r"(a[2]), "r"(a[3]), "r"(b0), "r"(b1));
}

__device__ __forceinline__ void ldmx4t(unsigned& d0, unsigned& d1,
                                       unsigned& d2, unsigned& d3, unsigned addr) {
    asm volatile(
        "ldmatrix.sync.aligned.m8n8.x4.trans.shared.b16 {%0,%1,%2,%3}, [%4];"
        : "=r"(d0), "=r"(d1), "=r"(d2), "=r"(d3)
        : "r"(addr));
}

__global__ __launch_bounds__(256, 4) void gcn_kernel() {
    __shared__ __align__(16) __nv_bfloat16 s_H[3 * 128 * 40];  // 3 planes x 128 j x 32 c (pad 40)

    const int tid = threadIdx.x;
    const int warp = tid >> 5, lane = tid & 31;
    const int g = lane >> 2, t = lane & 3;
    const int i0 = blockIdx.x * 128;
    const int ksp = blockIdx.y;
    const long jbase = (long)ksp * JR;

    float acc[16];
#pragma unroll
    for (int x = 0; x < 16; x++) acc[x] = 0.f;

    const unsigned sH_base = (unsigned)__cvta_generic_to_shared(s_H);
    const unsigned lm_row = lane & 15;
    const unsigned lm_col = (lane >> 4) * 8;
    const int r0 = i0 + warp * 16 + g;
    const unsigned* ap0 = g_A + (long)r0 * NP + (jbase >> 4);  // row g
    const unsigned* ap1 = ap0 + 8L * NP;                       // row g+8

    for (int jsb = 0; jsb < JR; jsb += 128) {
        __syncthreads();
        // stage H superblock: 3 planes x 128 j x 32 c bf16 = 24 KB
#pragma unroll
        for (int q = 0; q < 6; q++) {
            int id = tid + q * 256;
            int plane = id >> 9;
            int rem = id & 511;
            int row = rem >> 2, c4 = rem & 3;
            const __nv_bfloat16* src =
                g_H + ((long)plane * NN + jbase + jsb + row) * CH + c4 * 8;
            *(uint4*)(s_H + (plane * 128 + row) * 40 + c4 * 8) = *(const uint4*)src;
        }
        __syncthreads();

#pragma unroll
        for (int jo = 0; jo < 128; jo += 32) {
            const int jc = jsb + jo;
            const uint2 wg = *(const uint2*)(ap0 + (jc >> 4));   // row g,   32 cols
            const uint2 wh = *(const uint2*)(ap1 + (jc >> 4));   // row g+8, 32 cols
#pragma unroll
            for (int ks = 0; ks < 2; ks++) {
                const unsigned pg = ks ? wg.y : wg.x;
                const unsigned ph = ks ? wh.y : wh.x;
                unsigned e0 = (pg >> (4 * t)) & 0xFu;        // row g,   low cols
                unsigned e1 = (ph >> (4 * t)) & 0xFu;        // row g+8, low cols
                unsigned e2 = (pg >> (16 + 4 * t)) & 0xFu;   // row g,   high cols
                unsigned e3 = (ph >> (16 + 4 * t)) & 0xFu;   // row g+8, high cols

                unsigned A1[4], A2[4], A3[4];
#define MK(E, i)                                                              \
                {                                                             \
                    unsigned sel = ((E) & 3u) * 0x11u + ((E) >> 2) * 0x1100u + 0x4040u; \
                    A1[i] = __byte_perm(0x00008000u, 0x00003F00u, sel);       \
                    A2[i] = __byte_perm(0x00800000u, 0x003F0000u, sel);       \
                    A3[i] = __byte_perm(0x80000000u, 0x3F000000u, sel);       \
                }
                MK(e0, 0) MK(e1, 1) MK(e2, 2) MK(e3, 3)
#undef MK

#pragma unroll
                for (int m = 0; m < 3; m++) {
                    const unsigned* Am = (m == 0) ? A1 : ((m == 1) ? A2 : A3);
                    unsigned base = sH_base +
                        (((unsigned)(m * 128 + jo) + ks * 16 + lm_row) * 40 + lm_col) * 2;
                    unsigned b0, b1, b2, b3;
                    ldmx4t(b0, b1, b2, b3, base);          // n 0..15
                    mma_bf16(acc + 0, Am, b0, b1);
                    mma_bf16(acc + 4, Am, b2, b3);
                    ldmx4t(b0, b1, b2, b3, base + 32);     // n 16..31
                    mma_bf16(acc + 8, Am, b0, b1);
                    mma_bf16(acc + 12, Am, b2, b3);
                }
            }
        }
    }

    // fp32 partials (deterministic; reduced downstream)
    float* P = g_P + ((long)ksp * NN + i0 + warp * 16) * CH;
#pragma unroll
    for (int nt = 0; nt < 4; nt++) {
        int c = nt * 8 + 2 * t;
        *(float2*)(P + (g)     * CH + c) = make_float2(acc[nt * 4 + 0], acc[nt * 4 + 1]);
        *(float2*)(P + (g + 8) * CH + c) = make_float2(acc[nt * 4 + 2], acc[nt * 4 + 3]);
    }
}

// ---------------------------------------------------------------------------
// finish2: pooled sums of relu(gb1 + sum_s P[s]). grid 256 x 256.
// ---------------------------------------------------------------------------
__global__ __launch_bounds__(256, 2) void finish2_kernel(const float* __restrict__ bias) {
    __shared__ float sred[8][32];
    const int c = threadIdx.x & 31, w = threadIdx.x >> 5;
    const int j0 = blockIdx.x * 32;
    const float b = bias[c];
    float local = 0.f;
#pragma unroll
    for (int rr = 0; rr < 4; rr++) {
        const int row = j0 + w * 4 + rr;
        float s = 0.f;
#pragma unroll
        for (int p = 0; p < KSP; p++) s += g_P[((long)p * NN + row) * CH + c];
        local += fmaxf(b + s, 0.f);
    }
    sred[w][c] = local;
    __syncthreads();
    if (w == 0) {
        float tt = sred[0][c];
#pragma unroll
        for (int q = 1; q < 8; q++) tt += sred[q][c];
        g_pool[blockIdx.x * 32 + c] = tt;
    }
}

// ---------------------------------------------------------------------------
// final: pool -> fc0(relu) -> fc1 -> sigmoid. 1 block, 256 threads.
// ---------------------------------------------------------------------------
__global__ void final_kernel(const float* __restrict__ fcW0, const float* __restrict__ fcb0,
                             const float* __restrict__ fcW1, const float* __restrict__ fcb1,
                             float* __restrict__ out) {
    __shared__ float sred[8][32];
    __shared__ float pool[32];
    const int c = threadIdx.x & 31, w = threadIdx.x >> 5;
    float s = 0.f;
    for (int i = 0; i < 32; i++) s += g_pool[(w * 32 + i) * 32 + c];
    sred[w][c] = s;
    __syncthreads();
    if (w == 0) {
        float p = sred[0][c];
#pragma unroll
        for (int q = 1; q < 8; q++) p += sred[q][c];
        pool[c] = p;
        __syncwarp();
        float o = fcb0[c];
#pragma unroll
        for (int d = 0; d < 32; d++) o += pool[d] * fcW0[c * 32 + d];
        o = fmaxf(o, 0.f);
        float v = o * fcW1[c];
#pragma unroll
        for (int off = 16; off; off >>= 1) v += __shfl_xor_sync(0xffffffffu, v, off);
        if (c == 0) out[0] = 1.f / (1.f + expf(-(v + fcb1[0])));
    }
}

// ---------------------------------------------------------------------------
extern "C" void kernel_launch(void* const* d_in, const int* in_sizes, int n_in,
                              void* d_out, int out_size) {
    (void)in_sizes; (void)n_in; (void)out_size;
    const float* V    = (const float*)d_in[0];
    const int*   adj  = (const int*)d_in[1];
    const float* w1_0 = (const float*)d_in[2];
    const float* w2_0 = (const float*)d_in[3];
    const float* w3_0 = (const float*)d_in[4];
    const float* gb_0 = (const float*)d_in[5];
    const float* w1_1 = (const float*)d_in[6];
    const float* w2_1 = (const float*)d_in[7];
    const float* w3_1 = (const float*)d_in[8];
    const float* gb_1 = (const float*)d_in[9];
    const float* fcW0 = (const float*)d_in[10];
    const float* fcb0 = (const float*)d_in[11];
    const float* fcW1 = (const float*)d_in[12];
    const float* fcb1 = (const float*)d_in[13];

    dim3 gG(64, KSP);

    prep_kernel<<<256 + NN * NP / 256, 256>>>(adj, V, w1_0, w2_0, w3_0);  // repack + H(L1)
    gcn_kernel<<<gG, 256>>>();                                 // layer-1 masked matmul
    hgen_kernel<<<256, 256>>>(gb_0, w1_1, w2_1, w3_1);         // Z=relu(..), H planes (L2)
    gcn_kernel<<<gG, 256>>>();                                 // layer-2 masked matmul
    finish2_kernel<<<256, 256>>>(gb_1);                        // relu+bias+pool partials
    final_kernel<<<1, 256>>>(fcW0, fcb0, fcW1, fcb1, (float*)d_out);
}